// round 8
// baseline (speedup 1.0000x reference)
#include <cuda_runtime.h>
#include <cuda_bf16.h>
#include <cstdint>

// Problem constants
#define LSEQ  1024
#define BATCH 16
#define DIN   1024
#define NOUT  512
#define NLAY  4
#define MROWS (LSEQ*BATCH)   // 16384
#define KDIM  1024
#define NDIM  3072           // 6 * NOUT
#define NCH   16             // scan chunks
#define CH    64             // steps per chunk
#define NCHAIN 16384         // 2*B*NOUT

// GEMM tiling: block 128x256, BK=32, 256 threads, 8 warps (2x4) of 64x64
#define GK    32
#define NKT   (KDIM/GK)          // 32
#define A_BUF 4096               // floats: 4 planes x 1024
#define B_ST  264                // B k-row stride in floats (1056 B)
#define B_BUF (32 * B_ST)        // 8448 floats
#define SMEM_BYTES ((2*A_BUF + 2*B_BUF) * 4)   // 100352

// Scratch (device globals: allocation-free)
__device__ float g_x0[MROWS * DIN];        // x (tf32-valued) ping
__device__ float g_x1[MROWS * DIN];        // x (tf32-valued) pong
__device__ float g_u [MROWS * NDIM];       // gate activations
__device__ float g_wt[NLAY * KDIM * NDIM]; // tf32-converted weights [l][k][n]
__device__ float g_F [NCH * NCHAIN];
__device__ float g_C [NCH * NCHAIN];
__device__ float g_ce[NCH * NCHAIN];

__device__ __forceinline__ unsigned f2tf32(float x) {
    unsigned r;
    asm("cvt.rna.tf32.f32 %0, %1;" : "=r"(r) : "f"(x));
    return r;
}
__device__ __forceinline__ float tanh_fast(float x) {
    float y;
    asm("tanh.approx.f32 %0, %1;" : "=f"(y) : "f"(x));
    return y;
}
__device__ __forceinline__ uint32_t smem_u32(const void* p) {
    uint32_t a;
    asm("{ .reg .u64 t; cvta.to.shared.u64 t, %1; cvt.u32.u64 %0, t; }"
        : "=r"(a) : "l"(p));
    return a;
}
__device__ __forceinline__ void cp_async16(uint32_t dst, const void* src) {
    asm volatile("cp.async.cg.shared.global [%0], [%1], 16;"
                 :: "r"(dst), "l"(src) : "memory");
}
__device__ __forceinline__ void mma_tf32(float c[4],
                                         unsigned a0, unsigned a1, unsigned a2, unsigned a3,
                                         unsigned b0, unsigned b1) {
    asm volatile(
        "mma.sync.aligned.m16n8k8.row.col.f32.tf32.tf32.f32 "
        "{%0,%1,%2,%3}, {%4,%5,%6,%7}, {%8,%9}, {%0,%1,%2,%3};"
        : "+f"(c[0]), "+f"(c[1]), "+f"(c[2]), "+f"(c[3])
        : "r"(a0), "r"(a1), "r"(a2), "r"(a3), "r"(b0), "r"(b1));
}

// ---------------------------------------------------------------------------
// Weight pre-convert fp32 -> tf32 (once)
// ---------------------------------------------------------------------------
__global__ void wconv_kernel(const float* __restrict__ W, float* __restrict__ Wt) {
    int e = blockIdx.x * blockDim.x + threadIdx.x;
    float4 v = reinterpret_cast<const float4*>(W)[e];
    v.x = __uint_as_float(f2tf32(v.x));
    v.y = __uint_as_float(f2tf32(v.y));
    v.z = __uint_as_float(f2tf32(v.z));
    v.w = __uint_as_float(f2tf32(v.w));
    reinterpret_cast<float4*>(Wt)[e] = v;
}

// ---------------------------------------------------------------------------
// Embedding gather -> tf32-rounded x
// ---------------------------------------------------------------------------
__global__ void gather_kernel(const int* __restrict__ tok,
                              const float* __restrict__ emb,
                              float* __restrict__ out) {
    int e = blockIdx.x * blockDim.x + threadIdx.x;
    int row = e >> 8;
    int d4  = e & 255;
    int t = tok[row];
    float4 v = reinterpret_cast<const float4*>(emb + (size_t)t * DIN)[d4];
    v.x = __uint_as_float(f2tf32(v.x));
    v.y = __uint_as_float(f2tf32(v.y));
    v.z = __uint_as_float(f2tf32(v.z));
    v.w = __uint_as_float(f2tf32(v.w));
    reinterpret_cast<float4*>(out)[e] = v;
}

// ---------------------------------------------------------------------------
// TF32 GEMM: U = X(M,K)*W(K,N). Block 128x256, BK=32, 256 threads,
// 8 warps (2x4) of 64x64 warp tiles. mma.sync m16n8k8 tf32.
// A: manual staging, pair layout per k8 plane (plane stride 1024 floats):
//    As[plane*1024 + row*8] = {k0,k4,k1,k5}, +4 = {k2,k6,k3,k7}
//    -> fragment LDS.64 conflict-free.
// B: cp.async staging, [k][n] rows, stride 264 floats (8j+q banks, CF).
// Double-buffered; cp.async group per stage. Fused bias+sigmoid epilogue.
// ---------------------------------------------------------------------------
__global__ void __launch_bounds__(256, 1)
gemm_tf32_kernel(const float* __restrict__ A,
                 const float* __restrict__ W,
                 const float* __restrict__ bias,
                 float* __restrict__ U) {
    extern __shared__ float sm[];
    float* Asm = sm;                    // 2 * A_BUF
    float* Bsm = sm + 2 * A_BUF;        // 2 * B_BUF
    const uint32_t bsm_base = smem_u32(Bsm);

    const int tid  = threadIdx.x;
    const int lane = tid & 31;
    const int warp = tid >> 5;
    const int wm = warp >> 2;        // 0..1
    const int wn = warp & 3;         // 0..3
    const int rowBase = blockIdx.y * 128;
    const int colBase = blockIdx.x * 256;

    // A staging: row = tid>>1 (0..127), k-half = (tid&1)*16
    const int ar = tid >> 1;
    const int ah = tid & 1;
    const float* Ag = A + (size_t)(rowBase + ar) * KDIM + ah * 16;

    float4 pa[4];

    // B cp.async: 2048 16B chunks, 8 per thread. chunk v: r=v>>6 (k), c=v&63
    const float* Wg0 = W + colBase;

    auto cpB = [&](int buf, int kt) {
        const float* Wg = Wg0 + (size_t)(kt * GK) * NDIM;
        const uint32_t dst0 = bsm_base + buf * (B_BUF * 4);
        #pragma unroll
        for (int t = 0; t < 8; t++) {
            int v = tid + t * 256;
            int r = v >> 6, c = v & 63;
            cp_async16(dst0 + r * (B_ST * 4) + c * 16,
                       Wg + (size_t)r * NDIM + c * 4);
        }
        asm volatile("cp.async.commit_group;" ::: "memory");
    };
    auto ldgA = [&](int kt) {
        const float* Ag2 = Ag + kt * GK;
        #pragma unroll
        for (int e = 0; e < 4; e++)
            pa[e] = *reinterpret_cast<const float4*>(Ag2 + e * 4);
    };
    auto stsA = [&](int buf) {
        float* ap = &Asm[buf * A_BUF + (2 * ah) * 1024 + ar * 8];
        *reinterpret_cast<float4*>(ap)     = make_float4(pa[0].x, pa[1].x, pa[0].y, pa[1].y);
        *reinterpret_cast<float4*>(ap + 4) = make_float4(pa[0].z, pa[1].z, pa[0].w, pa[1].w);
        float* ap2 = ap + 1024;
        *reinterpret_cast<float4*>(ap2)     = make_float4(pa[2].x, pa[3].x, pa[2].y, pa[3].y);
        *reinterpret_cast<float4*>(ap2 + 4) = make_float4(pa[2].z, pa[3].z, pa[2].w, pa[3].w);
    };

    float acc[4][8][4];
    #pragma unroll
    for (int mf = 0; mf < 4; mf++)
        #pragma unroll
        for (int nf = 0; nf < 8; nf++)
            #pragma unroll
            for (int e = 0; e < 4; e++) acc[mf][nf][e] = 0.f;

    // prologue: stage 0
    cpB(0, 0);
    ldgA(0);
    stsA(0);
    asm volatile("cp.async.wait_group 0;" ::: "memory");
    __syncthreads();

    const int q = lane >> 2;     // 0..7
    const int j = lane & 3;      // 0..3
    int buf = 0;

    for (int kt = 0; kt < NKT; kt++) {
        if (kt < NKT - 1) {
            cpB(buf ^ 1, kt + 1);
            ldgA(kt + 1);
        }

        #pragma unroll
        for (int s = 0; s < 4; s++) {
            const float* ab = &Asm[buf * A_BUF + s * 1024];
            const float* bb = &Bsm[buf * B_BUF + (s * 8 + j) * B_ST + wn * 64 + q];
            float2 alo[4], ahi[4];
            #pragma unroll
            for (int mf = 0; mf < 4; mf++) {
                int r = wm * 64 + mf * 16 + q;
                alo[mf] = *reinterpret_cast<const float2*>(ab + r * 8 + j * 2);
                ahi[mf] = *reinterpret_cast<const float2*>(ab + (r + 8) * 8 + j * 2);
            }
            float b0[8], b1[8];
            #pragma unroll
            for (int nf = 0; nf < 8; nf++) {
                b0[nf] = bb[nf * 8];
                b1[nf] = bb[4 * B_ST + nf * 8];
            }
            #pragma unroll
            for (int mf = 0; mf < 4; mf++)
                #pragma unroll
                for (int nf = 0; nf < 8; nf++)
                    mma_tf32(acc[mf][nf],
                             __float_as_uint(alo[mf].x), __float_as_uint(ahi[mf].x),
                             __float_as_uint(alo[mf].y), __float_as_uint(ahi[mf].y),
                             __float_as_uint(b0[nf]),    __float_as_uint(b1[nf]));
        }

        if (kt < NKT - 1) {
            stsA(buf ^ 1);
            asm volatile("cp.async.wait_group 0;" ::: "memory");
            __syncthreads();
            buf ^= 1;
        }
    }

    // Epilogue: warp's 64-col slice lies within one 512-col block (64 | 512)
    const int wcol = colBase + wn * 64;
    const int dir  = wcol / 1536;
    const int cm   = wcol - dir * 1536;
    int btype = 0;
    const float* bptr = bias;
    if (cm >= 1024)      { btype = 2; bptr = bias + 1024 + dir * 512 + (cm - 1024); }
    else if (cm >= 512)  { btype = 1; bptr = bias + dir * 512 + (cm - 512); }

    #pragma unroll
    for (int nf = 0; nf < 8; nf++) {
        const int coff = nf * 8 + 2 * j;
        float bv0 = 0.f, bv1 = 0.f;
        if (btype) { bv0 = bptr[coff]; bv1 = bptr[coff + 1]; }
        const int col = wcol + coff;
        #pragma unroll
        for (int mf = 0; mf < 4; mf++) {
            const int row0 = rowBase + wm * 64 + mf * 16 + q;
            float v0 = acc[mf][nf][0], v1 = acc[mf][nf][1];
            float v2 = acc[mf][nf][2], v3 = acc[mf][nf][3];
            if (btype) {
                v0 = 1.f / (1.f + __expf(-(v0 + bv0)));
                v1 = 1.f / (1.f + __expf(-(v1 + bv1)));
                v2 = 1.f / (1.f + __expf(-(v2 + bv0)));
                v3 = 1.f / (1.f + __expf(-(v3 + bv1)));
            }
            *reinterpret_cast<float2*>(&U[(size_t)row0 * NDIM + col])
                = make_float2(v0, v1);
            *reinterpret_cast<float2*>(&U[(size_t)(row0 + 8) * NDIM + col])
                = make_float2(v2, v3);
        }
    }
}

// ---------------------------------------------------------------------------
// Chunked SRU scan (3-pass). Chain = dir*8192 + b*512 + i.
// ---------------------------------------------------------------------------
__global__ void scan1_kernel(const float* __restrict__ U,
                             float* __restrict__ Fo, float* __restrict__ Co) {
    const int idx = blockIdx.x * blockDim.x + threadIdx.x;
    const int chain = idx & (NCHAIN - 1);
    const int g = idx >> 14;
    const int dir = chain >> 13;
    const int b = (chain >> 9) & 15;
    const int i = chain & 511;

    const float* u0 = U + (size_t)b * NDIM + dir * 1536 + i;
    const int ustep = BATCH * NDIM;

    float F = 1.f, C = 0.f;
    const int l0 = g * CH;
    if (dir == 0) {
        #pragma unroll 8
        for (int t = 0; t < CH; t++) {
            const float* up = u0 + (size_t)(l0 + t) * ustep;
            float xt = __ldg(up);
            float f  = __ldg(up + 512);
            C = f * C + (1.f - f) * xt;
            F *= f;
        }
    } else {
        #pragma unroll 8
        for (int t = 0; t < CH; t++) {
            const float* up = u0 + (size_t)(l0 + CH - 1 - t) * ustep;
            float xt = __ldg(up);
            float f  = __ldg(up + 512);
            C = f * C + (1.f - f) * xt;
            F *= f;
        }
    }
    Fo[idx] = F;
    Co[idx] = C;
}

__global__ void scan2_kernel(const float* __restrict__ Fo, const float* __restrict__ Co,
                             float* __restrict__ ce, float* __restrict__ Cout) {
    const int chain = blockIdx.x * blockDim.x + threadIdx.x;
    const int dir = chain >> 13;
    const int b = (chain >> 9) & 15;
    const int i = chain & 511;

    float c = 0.f;
    #pragma unroll
    for (int t = 0; t < NCH; t++) {
        int g = dir ? (NCH - 1 - t) : t;
        ce[g * NCHAIN + chain] = c;
        c = Fo[g * NCHAIN + chain] * c + Co[g * NCHAIN + chain];
    }
    Cout[b * 1024 + dir * 512 + i] = c;
}

__global__ void scan3_kernel(const float* __restrict__ U,
                             const float* __restrict__ Xin,
                             const float* __restrict__ ce,
                             float* __restrict__ Xout,
                             int roundOut) {
    const int idx = blockIdx.x * blockDim.x + threadIdx.x;
    const int chain = idx & (NCHAIN - 1);
    const int g = idx >> 14;
    const int dir = chain >> 13;
    const int b = (chain >> 9) & 15;
    const int i = chain & 511;

    const float* u0 = U   + (size_t)b * NDIM + dir * 1536 + i;
    const float* x0 = Xin + (size_t)b * DIN  + dir * 512  + i;
    const size_t hoff = (size_t)b * DIN + dir * 512 + i;
    const int ustep = BATCH * NDIM;
    const int xstep = BATCH * DIN;

    float c = ce[g * NCHAIN + chain];
    const int l0 = g * CH;
    #pragma unroll 8
    for (int t = 0; t < CH; t++) {
        const int l = dir ? (l0 + CH - 1 - t) : (l0 + t);
        const float* up = u0 + (size_t)l * ustep;
        float xt = __ldg(up);
        float f  = __ldg(up + 512);
        float r  = __ldg(up + 1024);
        float xp = __ldg(x0 + (size_t)l * xstep);
        c = f * c + (1.f - f) * xt;
        float h = r * tanh_fast(c) + (1.f - r) * xp;
        if (roundOut) h = __uint_as_float(f2tf32(h));
        Xout[(size_t)l * xstep + hoff] = h;
    }
}

// ---------------------------------------------------------------------------
// Launch
// ---------------------------------------------------------------------------
extern "C" void kernel_launch(void* const* d_in, const int* in_sizes, int n_in,
                              void* d_out, int out_size) {
    const int*   tok = (const int*)d_in[0];
    const float* emb = (const float*)d_in[2];
    const float* Ws  = (const float*)d_in[3];
    const float* bs  = (const float*)d_in[4];
    float* out = (float*)d_out;

    float *x0, *x1, *u, *wt, *gF, *gC, *gce;
    cudaGetSymbolAddress((void**)&x0, g_x0);
    cudaGetSymbolAddress((void**)&x1, g_x1);
    cudaGetSymbolAddress((void**)&u,  g_u);
    cudaGetSymbolAddress((void**)&wt, g_wt);
    cudaGetSymbolAddress((void**)&gF, g_F);
    cudaGetSymbolAddress((void**)&gC, g_C);
    cudaGetSymbolAddress((void**)&gce, g_ce);

    cudaFuncSetAttribute(gemm_tf32_kernel,
                         cudaFuncAttributeMaxDynamicSharedMemorySize, SMEM_BYTES);

    // Pre-convert all weights to tf32
    wconv_kernel<<<(NLAY * KDIM * NDIM / 4) / 256, 256>>>(Ws, wt);

    // Embedding gather (tf32-rounded x)
    gather_kernel<<<(MROWS * DIN / 4) / 256, 256>>>(tok, emb, x0);

    float* xcur = x0;
    float* xalt = x1;
    float* hid_base = out + (size_t)MROWS * DIN;

    dim3 ggrid(NDIM / 256, MROWS / 128);   // (12, 128)
    const int scan_blocks = (NCH * NCHAIN) / 256;  // 1024

    for (int l = 0; l < NLAY; l++) {
        const float* Wl = wt + (size_t)l * KDIM * NDIM;
        const float* bl = bs + (size_t)l * 2048;
        gemm_tf32_kernel<<<ggrid, 256, SMEM_BYTES>>>(xcur, Wl, bl, u);

        float* xnext = (l == NLAY - 1) ? out : xalt;
        int roundNext = (l == NLAY - 1) ? 0 : 1;
        float* cout_l = hid_base + (size_t)l * BATCH * DIN;

        scan1_kernel<<<scan_blocks, 256>>>(u, gF, gC);
        scan2_kernel<<<NCHAIN / 256, 256>>>(gF, gC, gce, cout_l);
        scan3_kernel<<<scan_blocks, 256>>>(u, xcur, gce, xnext, roundNext);

        xalt = xcur;
        xcur = xnext;
    }
}

// round 9
// speedup vs baseline: 1.6585x; 1.6585x over previous
#include <cuda_runtime.h>
#include <cuda_fp16.h>
#include <cstdint>

// Problem constants
#define LSEQ  1024
#define BATCH 16
#define DIN   1024
#define NOUT  512
#define NLAY  4
#define MROWS (LSEQ*BATCH)   // 16384
#define KDIM  1024
#define NDIM  3072           // 6 * NOUT
#define NCH   16             // scan chunks
#define CH    64             // steps per chunk
#define NCHAIN 16384         // 2*B*NOUT

// GEMM: block 128x256, BK=32, 256 threads, 8 warps (2x4) of 64x64 tiles
#define GK    32
#define NKT   (KDIM/GK)      // 32
#define A_BUF_B 8192         // 2 planes x 128 rows x 32B
#define B_ROW_B 1056         // 264 uints
#define B_BUF_B (16 * B_ROW_B)   // 16896
#define SMEM_BYTES (2*A_BUF_B + 2*B_BUF_B)   // 50176

// Scratch (device globals: allocation-free)
__device__ float    g_x0[MROWS * DIN];          // exact fp32 x ping
__device__ float    g_x1[MROWS * DIN];          // exact fp32 x pong
__device__ __half   g_xh[MROWS * DIN];          // half x, permuted+swizzled
__device__ unsigned g_wh[NLAY * (KDIM/2) * NDIM]; // pair-packed half2 W
__device__ float    g_u [MROWS * NDIM];
__device__ float    g_F [NCH * NCHAIN];
__device__ float    g_C [NCH * NCHAIN];
__device__ float    g_ce[NCH * NCHAIN];

__device__ __forceinline__ float tanh_fast(float x) {
    float y;
    asm("tanh.approx.f32 %0, %1;" : "=f"(y) : "f"(x));
    return y;
}
__device__ __forceinline__ uint32_t smem_u32(const void* p) {
    uint32_t a;
    asm("{ .reg .u64 t; cvta.to.shared.u64 t, %1; cvt.u32.u64 %0, t; }"
        : "=r"(a) : "l"(p));
    return a;
}
__device__ __forceinline__ void cp_async16(uint32_t dst, const void* src) {
    asm volatile("cp.async.cg.shared.global [%0], [%1], 16;"
                 :: "r"(dst), "l"(src) : "memory");
}
__device__ __forceinline__ unsigned packh2(float lo, float hi) {
    __half2 h = __floats2half2_rn(lo, hi);
    return *reinterpret_cast<unsigned*>(&h);
}
__device__ __forceinline__ void mma_f16(float c[4],
                                        unsigned a0, unsigned a1,
                                        unsigned a2, unsigned a3,
                                        unsigned b0, unsigned b1) {
    asm volatile(
        "mma.sync.aligned.m16n8k16.row.col.f32.f16.f16.f32 "
        "{%0,%1,%2,%3}, {%4,%5,%6,%7}, {%8,%9}, {%0,%1,%2,%3};"
        : "+f"(c[0]), "+f"(c[1]), "+f"(c[2]), "+f"(c[3])
        : "r"(a0), "r"(a1), "r"(a2), "r"(a3), "r"(b0), "r"(b1));
}
// position of even k-pair start within permuted+swizzled row
__device__ __forceinline__ int permpos_pair(int k, int row) {
    int pp = (k & 15) >> 1;
    return (k & ~15) + ((((pp & 3) ^ (row & 3))) << 2) + ((pp >> 2) << 1);
}

// ---------------------------------------------------------------------------
// Weight pre-pack (once): wh[l][p][n] = half2( W[l][2p][n], W[l][2p+1][n] )
// ---------------------------------------------------------------------------
__global__ void wconv_kernel(const float* __restrict__ W, unsigned* __restrict__ Wp) {
    int e = blockIdx.x * blockDim.x + threadIdx.x;   // over NLAY*512*768
    int n4 = e % (NDIM / 4);
    int tmp = e / (NDIM / 4);
    int p = tmp % (KDIM / 2);
    int l = tmp / (KDIM / 2);
    const float* base = W + (size_t)l * KDIM * NDIM + (size_t)(2 * p) * NDIM + n4 * 4;
    float4 r0 = *reinterpret_cast<const float4*>(base);
    float4 r1 = *reinterpret_cast<const float4*>(base + NDIM);
    uint4 u;
    u.x = packh2(r0.x, r1.x);
    u.y = packh2(r0.y, r1.y);
    u.z = packh2(r0.z, r1.z);
    u.w = packh2(r0.w, r1.w);
    reinterpret_cast<uint4*>(Wp + ((size_t)l * (KDIM/2) + p) * NDIM)[n4] = u;
}

// ---------------------------------------------------------------------------
// Embedding gather -> exact fp32 x + permuted half copy
// ---------------------------------------------------------------------------
__global__ void gather_kernel(const int* __restrict__ tok,
                              const float* __restrict__ emb,
                              float* __restrict__ out,
                              __half* __restrict__ outH) {
    int e = blockIdx.x * blockDim.x + threadIdx.x;
    int row = e >> 8;
    int d4  = e & 255;
    int t = tok[row];
    float4 v = reinterpret_cast<const float4*>(emb + (size_t)t * DIN)[d4];
    reinterpret_cast<float4*>(out)[e] = v;
    int k0 = d4 * 4;
    __half2 h01 = __floats2half2_rn(v.x, v.y);
    __half2 h23 = __floats2half2_rn(v.z, v.w);
    __half* xr = outH + (size_t)row * DIN;
    *reinterpret_cast<__half2*>(xr + permpos_pair(k0, row))     = h01;
    *reinterpret_cast<__half2*>(xr + permpos_pair(k0 + 2, row)) = h23;
}

// ---------------------------------------------------------------------------
// FP16 GEMM: U = X(M,K)*W(K,N). mma.sync m16n8k16 f16 -> fp32 acc.
// A smem: per k-step plane s (4096B), row r 32B: chunk j' = j^(r&3) 8B =
//   halves {k2j, k2j+1, k2j+8, k2j+9}  (one LDS.64 = a0,a2; row+8 = a1,a3)
// B smem: pair rows p (k pair), 264 uints stride; b0 reg = {even k lo, odd hi}
// Both staged by straight cp.async from pre-permuted global layouts.
// Fused bias+sigmoid epilogue.
// ---------------------------------------------------------------------------
__global__ void __launch_bounds__(256, 1)
gemm_f16_kernel(const __half* __restrict__ Xh,
                const unsigned* __restrict__ Wp,
                const float* __restrict__ bias,
                float* __restrict__ U) {
    extern __shared__ char sm[];
    char* Abuf = sm;                    // 2 * A_BUF_B
    char* Bbuf = sm + 2 * A_BUF_B;      // 2 * B_BUF_B
    const uint32_t a_s = smem_u32(Abuf);
    const uint32_t b_s = smem_u32(Bbuf);

    const int tid  = threadIdx.x;
    const int lane = tid & 31;
    const int warp = tid >> 5;
    const int wm = warp >> 2;        // 0..1
    const int wn = warp & 3;         // 0..3
    const int q = lane >> 2;         // 0..7
    const int j = lane & 3;          // 0..3
    const int rowBase = blockIdx.y * 128;
    const int colBase = blockIdx.x * 256;

    const char* Ag = reinterpret_cast<const char*>(Xh + (size_t)rowBase * DIN);
    const unsigned* Bg = Wp + colBase;

    float acc[4][8][4];
    #pragma unroll
    for (int mf = 0; mf < 4; mf++)
        #pragma unroll
        for (int nf = 0; nf < 8; nf++)
            #pragma unroll
            for (int e = 0; e < 4; e++) acc[mf][nf][e] = 0.f;

    auto cpStage = [&](int buf, int kt) {
        // A: 128 rows x 64B = 512 x 16B chunks (2/thread)
        #pragma unroll
        for (int t = 0; t < 2; t++) {
            int v = tid + t * 256;
            int r = v >> 2, c = v & 3;
            cp_async16(a_s + buf * A_BUF_B + (c >> 1) * 4096 + r * 32 + (c & 1) * 16,
                       Ag + (size_t)r * (DIN * 2) + kt * 64 + c * 16);
        }
        // B: 16 pair-rows x 256 uints = 1024 x 16B chunks (4/thread)
        #pragma unroll
        for (int t = 0; t < 4; t++) {
            int v = tid + t * 256;
            int p = v >> 6, nc = v & 63;
            cp_async16(b_s + buf * B_BUF_B + p * B_ROW_B + nc * 16,
                       Bg + (size_t)(kt * 16 + p) * NDIM + nc * 4);
        }
        asm volatile("cp.async.commit_group;" ::: "memory");
    };

    cpStage(0, 0);
    int buf = 0;

    for (int kt = 0; kt < NKT; kt++) {
        asm volatile("cp.async.wait_group 0;" ::: "memory");
        __syncthreads();
        if (kt < NKT - 1) cpStage(buf ^ 1, kt + 1);

        #pragma unroll
        for (int s = 0; s < 2; s++) {
            const char* ab = Abuf + buf * A_BUF_B + s * 4096;
            uint2 alo[4], ahi[4];
            #pragma unroll
            for (int mf = 0; mf < 4; mf++) {
                int r = wm * 64 + mf * 16 + q;
                int sw = (j ^ (r & 3)) * 8;
                alo[mf] = *reinterpret_cast<const uint2*>(ab + r * 32 + sw);
                ahi[mf] = *reinterpret_cast<const uint2*>(ab + (r + 8) * 32 + sw);
            }
            const char* bb = Bbuf + buf * B_BUF_B + (s * 8 + j) * B_ROW_B
                           + (wn * 64 + q) * 4;
            unsigned b0[8], b1[8];
            #pragma unroll
            for (int nf = 0; nf < 8; nf++) {
                b0[nf] = *reinterpret_cast<const unsigned*>(bb + nf * 32);
                b1[nf] = *reinterpret_cast<const unsigned*>(bb + 4 * B_ROW_B + nf * 32);
            }
            #pragma unroll
            for (int mf = 0; mf < 4; mf++)
                #pragma unroll
                for (int nf = 0; nf < 8; nf++)
                    mma_f16(acc[mf][nf],
                            alo[mf].x, ahi[mf].x, alo[mf].y, ahi[mf].y,
                            b0[nf], b1[nf]);
        }
        buf ^= 1;
    }

    // Epilogue: warp's 64-col slice lies within one 512-col block (64 | 512)
    const int wcol = colBase + wn * 64;
    const int dir  = wcol / 1536;
    const int cm   = wcol - dir * 1536;
    int btype = 0;
    const float* bptr = bias;
    if (cm >= 1024)      { btype = 2; bptr = bias + 1024 + dir * 512 + (cm - 1024); }
    else if (cm >= 512)  { btype = 1; bptr = bias + dir * 512 + (cm - 512); }

    #pragma unroll
    for (int nf = 0; nf < 8; nf++) {
        const int coff = nf * 8 + 2 * j;
        float bv0 = 0.f, bv1 = 0.f;
        if (btype) { bv0 = bptr[coff]; bv1 = bptr[coff + 1]; }
        const int col = wcol + coff;
        #pragma unroll
        for (int mf = 0; mf < 4; mf++) {
            const int row0 = rowBase + wm * 64 + mf * 16 + q;
            float v0 = acc[mf][nf][0], v1 = acc[mf][nf][1];
            float v2 = acc[mf][nf][2], v3 = acc[mf][nf][3];
            if (btype) {
                v0 = 1.f / (1.f + __expf(-(v0 + bv0)));
                v1 = 1.f / (1.f + __expf(-(v1 + bv1)));
                v2 = 1.f / (1.f + __expf(-(v2 + bv0)));
                v3 = 1.f / (1.f + __expf(-(v3 + bv1)));
            }
            *reinterpret_cast<float2*>(&U[(size_t)row0 * NDIM + col])
                = make_float2(v0, v1);
            *reinterpret_cast<float2*>(&U[(size_t)(row0 + 8) * NDIM + col])
                = make_float2(v2, v3);
        }
    }
}

// ---------------------------------------------------------------------------
// Chunked SRU scan (3-pass). Chain = dir*8192 + b*512 + i.
// ---------------------------------------------------------------------------
__global__ void scan1_kernel(const float* __restrict__ U,
                             float* __restrict__ Fo, float* __restrict__ Co) {
    const int idx = blockIdx.x * blockDim.x + threadIdx.x;
    const int chain = idx & (NCHAIN - 1);
    const int g = idx >> 14;
    const int dir = chain >> 13;
    const int b = (chain >> 9) & 15;
    const int i = chain & 511;

    const float* u0 = U + (size_t)b * NDIM + dir * 1536 + i;
    const int ustep = BATCH * NDIM;

    float F = 1.f, C = 0.f;
    const int l0 = g * CH;
    if (dir == 0) {
        #pragma unroll 8
        for (int t = 0; t < CH; t++) {
            const float* up = u0 + (size_t)(l0 + t) * ustep;
            float xt = __ldg(up);
            float f  = __ldg(up + 512);
            C = f * C + (1.f - f) * xt;
            F *= f;
        }
    } else {
        #pragma unroll 8
        for (int t = 0; t < CH; t++) {
            const float* up = u0 + (size_t)(l0 + CH - 1 - t) * ustep;
            float xt = __ldg(up);
            float f  = __ldg(up + 512);
            C = f * C + (1.f - f) * xt;
            F *= f;
        }
    }
    Fo[idx] = F;
    Co[idx] = C;
}

__global__ void scan2_kernel(const float* __restrict__ Fo, const float* __restrict__ Co,
                             float* __restrict__ ce, float* __restrict__ Cout) {
    const int chain = blockIdx.x * blockDim.x + threadIdx.x;
    const int dir = chain >> 13;
    const int b = (chain >> 9) & 15;
    const int i = chain & 511;

    float c = 0.f;
    #pragma unroll
    for (int t = 0; t < NCH; t++) {
        int g = dir ? (NCH - 1 - t) : t;
        ce[g * NCHAIN + chain] = c;
        c = Fo[g * NCHAIN + chain] * c + Co[g * NCHAIN + chain];
    }
    Cout[b * 1024 + dir * 512 + i] = c;
}

__global__ void scan3_kernel(const float* __restrict__ U,
                             const float* __restrict__ Xin,
                             const float* __restrict__ ce,
                             float* __restrict__ Xout,
                             __half* __restrict__ XoutH) {   // may be null
    const int idx = blockIdx.x * blockDim.x + threadIdx.x;
    const int chain = idx & (NCHAIN - 1);
    const int g = idx >> 14;
    const int dir = chain >> 13;
    const int b = (chain >> 9) & 15;
    const int i = chain & 511;

    const float* u0 = U   + (size_t)b * NDIM + dir * 1536 + i;
    const float* x0 = Xin + (size_t)b * DIN  + dir * 512  + i;
    const size_t hoff = (size_t)b * DIN + dir * 512 + i;
    const int ustep = BATCH * NDIM;
    const int xstep = BATCH * DIN;

    // half-buffer position (permuted + row-swizzled; row&3 == b&3)
    const int kk = dir * 512 + i;
    const int pp = (kk & 15) >> 1;
    const int pos = (kk & ~15) + (((pp & 3) ^ (b & 3)) << 2)
                  + ((pp >> 2) << 1) + (kk & 1);
    const size_t hposoff = (size_t)b * DIN + pos;

    float c = ce[g * NCHAIN + chain];
    const int l0 = g * CH;
    #pragma unroll 8
    for (int t = 0; t < CH; t++) {
        const int l = dir ? (l0 + CH - 1 - t) : (l0 + t);
        const float* up = u0 + (size_t)l * ustep;
        float xt = __ldg(up);
        float f  = __ldg(up + 512);
        float r  = __ldg(up + 1024);
        float xp = __ldg(x0 + (size_t)l * xstep);
        c = f * c + (1.f - f) * xt;
        float h = r * tanh_fast(c) + (1.f - r) * xp;
        Xout[(size_t)l * xstep + hoff] = h;
        if (XoutH)
            XoutH[(size_t)l * xstep + hposoff] = __float2half_rn(h);
    }
}

// ---------------------------------------------------------------------------
// Launch
// ---------------------------------------------------------------------------
extern "C" void kernel_launch(void* const* d_in, const int* in_sizes, int n_in,
                              void* d_out, int out_size) {
    const int*   tok = (const int*)d_in[0];
    const float* emb = (const float*)d_in[2];
    const float* Ws  = (const float*)d_in[3];
    const float* bs  = (const float*)d_in[4];
    float* out = (float*)d_out;

    float *x0, *x1, *u, *gF, *gC, *gce;
    __half* xh;
    unsigned* wh;
    cudaGetSymbolAddress((void**)&x0, g_x0);
    cudaGetSymbolAddress((void**)&x1, g_x1);
    cudaGetSymbolAddress((void**)&xh, g_xh);
    cudaGetSymbolAddress((void**)&wh, g_wh);
    cudaGetSymbolAddress((void**)&u,  g_u);
    cudaGetSymbolAddress((void**)&gF, g_F);
    cudaGetSymbolAddress((void**)&gC, g_C);
    cudaGetSymbolAddress((void**)&gce, g_ce);

    cudaFuncSetAttribute(gemm_f16_kernel,
                         cudaFuncAttributeMaxDynamicSharedMemorySize, SMEM_BYTES);

    // Pre-pack weights to half2 pairs
    wconv_kernel<<<(NLAY * (KDIM/2) * (NDIM/4)) / 256, 256>>>(Ws, wh);

    // Embedding gather
    gather_kernel<<<(MROWS * DIN / 4) / 256, 256>>>(tok, emb, x0, xh);

    float* xcur = x0;
    float* xalt = x1;
    float* hid_base = out + (size_t)MROWS * DIN;

    dim3 ggrid(NDIM / 256, MROWS / 128);        // (12, 128)
    const int scan_blocks = (NCH * NCHAIN) / 256;  // 1024

    for (int l = 0; l < NLAY; l++) {
        const unsigned* Wl = wh + (size_t)l * (KDIM/2) * NDIM;
        const float* bl = bs + (size_t)l * 2048;
        gemm_f16_kernel<<<ggrid, 256, SMEM_BYTES>>>(xh, Wl, bl, u);

        float* xnext = (l == NLAY - 1) ? out : xalt;
        __half* xhnext = (l == NLAY - 1) ? nullptr : xh;
        float* cout_l = hid_base + (size_t)l * BATCH * DIN;

        scan1_kernel<<<scan_blocks, 256>>>(u, gF, gC);
        scan2_kernel<<<NCHAIN / 256, 256>>>(gF, gC, gce, cout_l);
        scan3_kernel<<<scan_blocks, 256>>>(u, xcur, gce, xnext, xhnext);

        xalt = xcur;
        xcur = xnext;
    }
}

// round 10
// speedup vs baseline: 1.7014x; 1.0258x over previous
#include <cuda_runtime.h>
#include <cuda_fp16.h>
#include <cstdint>

// Problem constants
#define LSEQ  1024
#define BATCH 16
#define DIN   1024
#define NOUT  512
#define NLAY  4
#define MROWS (LSEQ*BATCH)   // 16384
#define KDIM  1024
#define NDIM  3072           // 6 * NOUT
#define NCH   16             // scan chunks
#define CH    64             // steps per chunk
#define NCHAIN 16384         // 2*B*NOUT

// GEMM: block 128x256, BK=32, 256 threads, 8 warps (2x4) of 64x64 tiles
#define GK    32
#define NKT   (KDIM/GK)      // 32
#define A_BUF_B 8192         // 2 planes x 128 rows x 32B
#define B_ROW_B 1056         // 264 uints
#define B_BUF_B (16 * B_ROW_B)   // 16896
#define SMEM_BYTES (2*A_BUF_B + 2*B_BUF_B)   // 50176

// Scratch (device globals: allocation-free)
__device__ float    g_x0[MROWS * DIN];          // exact fp32 x ping
__device__ float    g_x1[MROWS * DIN];          // exact fp32 x pong
__device__ __half   g_xh[MROWS * DIN];          // half x, permuted+swizzled
__device__ unsigned g_wh[NLAY * (KDIM/2) * NDIM]; // pair-packed half2 W
__device__ __half   g_u [MROWS * NDIM];         // gate activations (fp16)
__device__ float    g_F [NCH * NCHAIN];
__device__ float    g_C [NCH * NCHAIN];
__device__ float    g_ce[NCH * NCHAIN];

__device__ __forceinline__ float tanh_fast(float x) {
    float y;
    asm("tanh.approx.f32 %0, %1;" : "=f"(y) : "f"(x));
    return y;
}
__device__ __forceinline__ uint32_t smem_u32(const void* p) {
    uint32_t a;
    asm("{ .reg .u64 t; cvta.to.shared.u64 t, %1; cvt.u32.u64 %0, t; }"
        : "=r"(a) : "l"(p));
    return a;
}
__device__ __forceinline__ void cp_async16(uint32_t dst, const void* src) {
    asm volatile("cp.async.cg.shared.global [%0], [%1], 16;"
                 :: "r"(dst), "l"(src) : "memory");
}
__device__ __forceinline__ unsigned packh2(float lo, float hi) {
    __half2 h = __floats2half2_rn(lo, hi);
    return *reinterpret_cast<unsigned*>(&h);
}
__device__ __forceinline__ void mma_f16(float c[4],
                                        unsigned a0, unsigned a1,
                                        unsigned a2, unsigned a3,
                                        unsigned b0, unsigned b1) {
    asm volatile(
        "mma.sync.aligned.m16n8k16.row.col.f32.f16.f16.f32 "
        "{%0,%1,%2,%3}, {%4,%5,%6,%7}, {%8,%9}, {%0,%1,%2,%3};"
        : "+f"(c[0]), "+f"(c[1]), "+f"(c[2]), "+f"(c[3])
        : "r"(a0), "r"(a1), "r"(a2), "r"(a3), "r"(b0), "r"(b1));
}
// position of even k-pair start within permuted+swizzled row
__device__ __forceinline__ int permpos_pair(int k, int row) {
    int pp = (k & 15) >> 1;
    return (k & ~15) + ((((pp & 3) ^ (row & 3))) << 2) + ((pp >> 2) << 1);
}

// ---------------------------------------------------------------------------
// Weight pre-pack (once): wh[l][p][n] = half2( W[l][2p][n], W[l][2p+1][n] )
// ---------------------------------------------------------------------------
__global__ void wconv_kernel(const float* __restrict__ W, unsigned* __restrict__ Wp) {
    int e = blockIdx.x * blockDim.x + threadIdx.x;
    int n4 = e % (NDIM / 4);
    int tmp = e / (NDIM / 4);
    int p = tmp % (KDIM / 2);
    int l = tmp / (KDIM / 2);
    const float* base = W + (size_t)l * KDIM * NDIM + (size_t)(2 * p) * NDIM + n4 * 4;
    float4 r0 = *reinterpret_cast<const float4*>(base);
    float4 r1 = *reinterpret_cast<const float4*>(base + NDIM);
    uint4 u;
    u.x = packh2(r0.x, r1.x);
    u.y = packh2(r0.y, r1.y);
    u.z = packh2(r0.z, r1.z);
    u.w = packh2(r0.w, r1.w);
    reinterpret_cast<uint4*>(Wp + ((size_t)l * (KDIM/2) + p) * NDIM)[n4] = u;
}

// ---------------------------------------------------------------------------
// Embedding gather -> exact fp32 x + permuted half copy
// ---------------------------------------------------------------------------
__global__ void gather_kernel(const int* __restrict__ tok,
                              const float* __restrict__ emb,
                              float* __restrict__ out,
                              __half* __restrict__ outH) {
    int e = blockIdx.x * blockDim.x + threadIdx.x;
    int row = e >> 8;
    int d4  = e & 255;
    int t = tok[row];
    float4 v = reinterpret_cast<const float4*>(emb + (size_t)t * DIN)[d4];
    reinterpret_cast<float4*>(out)[e] = v;
    int k0 = d4 * 4;
    __half2 h01 = __floats2half2_rn(v.x, v.y);
    __half2 h23 = __floats2half2_rn(v.z, v.w);
    __half* xr = outH + (size_t)row * DIN;
    *reinterpret_cast<__half2*>(xr + permpos_pair(k0, row))     = h01;
    *reinterpret_cast<__half2*>(xr + permpos_pair(k0 + 2, row)) = h23;
}

// ---------------------------------------------------------------------------
// FP16 GEMM: U = X(M,K)*W(K,N). mma.sync m16n8k16 f16 -> fp32 acc.
// A smem: per k-step plane s (4096B), row r 32B: chunk j' = j^(r&3) 8B
// B smem: pair rows, 1056B stride; b0 reg = {even k lo, odd hi}
// Straight cp.async staging from pre-permuted global layouts.
// Fused bias+sigmoid epilogue; U stored as fp16 (half2 stores).
// ---------------------------------------------------------------------------
__global__ void __launch_bounds__(256, 1)
gemm_f16_kernel(const __half* __restrict__ Xh,
                const unsigned* __restrict__ Wp,
                const float* __restrict__ bias,
                __half* __restrict__ U) {
    extern __shared__ char sm[];
    char* Abuf = sm;                    // 2 * A_BUF_B
    char* Bbuf = sm + 2 * A_BUF_B;      // 2 * B_BUF_B
    const uint32_t a_s = smem_u32(Abuf);
    const uint32_t b_s = smem_u32(Bbuf);

    const int tid  = threadIdx.x;
    const int lane = tid & 31;
    const int warp = tid >> 5;
    const int wm = warp >> 2;        // 0..1
    const int wn = warp & 3;         // 0..3
    const int q = lane >> 2;         // 0..7
    const int j = lane & 3;          // 0..3
    const int rowBase = blockIdx.y * 128;
    const int colBase = blockIdx.x * 256;

    const char* Ag = reinterpret_cast<const char*>(Xh + (size_t)rowBase * DIN);
    const unsigned* Bg = Wp + colBase;

    float acc[4][8][4];
    #pragma unroll
    for (int mf = 0; mf < 4; mf++)
        #pragma unroll
        for (int nf = 0; nf < 8; nf++)
            #pragma unroll
            for (int e = 0; e < 4; e++) acc[mf][nf][e] = 0.f;

    auto cpStage = [&](int buf, int kt) {
        #pragma unroll
        for (int t = 0; t < 2; t++) {
            int v = tid + t * 256;
            int r = v >> 2, c = v & 3;
            cp_async16(a_s + buf * A_BUF_B + (c >> 1) * 4096 + r * 32 + (c & 1) * 16,
                       Ag + (size_t)r * (DIN * 2) + kt * 64 + c * 16);
        }
        #pragma unroll
        for (int t = 0; t < 4; t++) {
            int v = tid + t * 256;
            int p = v >> 6, nc = v & 63;
            cp_async16(b_s + buf * B_BUF_B + p * B_ROW_B + nc * 16,
                       Bg + (size_t)(kt * 16 + p) * NDIM + nc * 4);
        }
        asm volatile("cp.async.commit_group;" ::: "memory");
    };

    cpStage(0, 0);
    int buf = 0;

    for (int kt = 0; kt < NKT; kt++) {
        asm volatile("cp.async.wait_group 0;" ::: "memory");
        __syncthreads();
        if (kt < NKT - 1) cpStage(buf ^ 1, kt + 1);

        #pragma unroll
        for (int s = 0; s < 2; s++) {
            const char* ab = Abuf + buf * A_BUF_B + s * 4096;
            uint2 alo[4], ahi[4];
            #pragma unroll
            for (int mf = 0; mf < 4; mf++) {
                int r = wm * 64 + mf * 16 + q;
                int sw = (j ^ (r & 3)) * 8;
                alo[mf] = *reinterpret_cast<const uint2*>(ab + r * 32 + sw);
                ahi[mf] = *reinterpret_cast<const uint2*>(ab + (r + 8) * 32 + sw);
            }
            const char* bb = Bbuf + buf * B_BUF_B + (s * 8 + j) * B_ROW_B
                           + (wn * 64 + q) * 4;
            unsigned b0[8], b1[8];
            #pragma unroll
            for (int nf = 0; nf < 8; nf++) {
                b0[nf] = *reinterpret_cast<const unsigned*>(bb + nf * 32);
                b1[nf] = *reinterpret_cast<const unsigned*>(bb + 4 * B_ROW_B + nf * 32);
            }
            #pragma unroll
            for (int mf = 0; mf < 4; mf++)
                #pragma unroll
                for (int nf = 0; nf < 8; nf++)
                    mma_f16(acc[mf][nf],
                            alo[mf].x, ahi[mf].x, alo[mf].y, ahi[mf].y,
                            b0[nf], b1[nf]);
        }
        buf ^= 1;
    }

    // Epilogue: warp's 64-col slice lies within one 512-col block (64 | 512)
    const int wcol = colBase + wn * 64;
    const int dir  = wcol / 1536;
    const int cm   = wcol - dir * 1536;
    int btype = 0;
    const float* bptr = bias;
    if (cm >= 1024)      { btype = 2; bptr = bias + 1024 + dir * 512 + (cm - 1024); }
    else if (cm >= 512)  { btype = 1; bptr = bias + dir * 512 + (cm - 512); }

    #pragma unroll
    for (int nf = 0; nf < 8; nf++) {
        const int coff = nf * 8 + 2 * j;
        float bv0 = 0.f, bv1 = 0.f;
        if (btype) { bv0 = bptr[coff]; bv1 = bptr[coff + 1]; }
        const int col = wcol + coff;
        #pragma unroll
        for (int mf = 0; mf < 4; mf++) {
            const int row0 = rowBase + wm * 64 + mf * 16 + q;
            float v0 = acc[mf][nf][0], v1 = acc[mf][nf][1];
            float v2 = acc[mf][nf][2], v3 = acc[mf][nf][3];
            if (btype) {
                v0 = 1.f / (1.f + __expf(-(v0 + bv0)));
                v1 = 1.f / (1.f + __expf(-(v1 + bv1)));
                v2 = 1.f / (1.f + __expf(-(v2 + bv0)));
                v3 = 1.f / (1.f + __expf(-(v3 + bv1)));
            }
            *reinterpret_cast<__half2*>(&U[(size_t)row0 * NDIM + col])
                = __floats2half2_rn(v0, v1);
            *reinterpret_cast<__half2*>(&U[(size_t)(row0 + 8) * NDIM + col])
                = __floats2half2_rn(v2, v3);
        }
    }
}

// ---------------------------------------------------------------------------
// Chunked SRU scan (3-pass). Chain = dir*8192 + b*512 + i. U is fp16.
// ---------------------------------------------------------------------------
__global__ void scan1_kernel(const __half* __restrict__ U,
                             float* __restrict__ Fo, float* __restrict__ Co) {
    const int idx = blockIdx.x * blockDim.x + threadIdx.x;
    const int chain = idx & (NCHAIN - 1);
    const int g = idx >> 14;
    const int dir = chain >> 13;
    const int b = (chain >> 9) & 15;
    const int i = chain & 511;

    const __half* u0 = U + (size_t)b * NDIM + dir * 1536 + i;
    const int ustep = BATCH * NDIM;

    float F = 1.f, C = 0.f;
    const int l0 = g * CH;
    if (dir == 0) {
        #pragma unroll 8
        for (int t = 0; t < CH; t++) {
            const __half* up = u0 + (size_t)(l0 + t) * ustep;
            float xt = __half2float(__ldg(up));
            float f  = __half2float(__ldg(up + 512));
            C = f * C + (1.f - f) * xt;
            F *= f;
        }
    } else {
        #pragma unroll 8
        for (int t = 0; t < CH; t++) {
            const __half* up = u0 + (size_t)(l0 + CH - 1 - t) * ustep;
            float xt = __half2float(__ldg(up));
            float f  = __half2float(__ldg(up + 512));
            C = f * C + (1.f - f) * xt;
            F *= f;
        }
    }
    Fo[idx] = F;
    Co[idx] = C;
}

__global__ void scan2_kernel(const float* __restrict__ Fo, const float* __restrict__ Co,
                             float* __restrict__ ce, float* __restrict__ Cout) {
    const int chain = blockIdx.x * blockDim.x + threadIdx.x;
    const int dir = chain >> 13;
    const int b = (chain >> 9) & 15;
    const int i = chain & 511;

    float c = 0.f;
    #pragma unroll
    for (int t = 0; t < NCH; t++) {
        int g = dir ? (NCH - 1 - t) : t;
        ce[g * NCHAIN + chain] = c;
        c = Fo[g * NCHAIN + chain] * c + Co[g * NCHAIN + chain];
    }
    Cout[b * 1024 + dir * 512 + i] = c;
}

__global__ void scan3_kernel(const __half* __restrict__ U,
                             const float* __restrict__ Xin,
                             const float* __restrict__ ce,
                             float* __restrict__ Xout,
                             __half* __restrict__ XoutH) {   // may be null
    const int idx = blockIdx.x * blockDim.x + threadIdx.x;
    const int chain = idx & (NCHAIN - 1);
    const int g = idx >> 14;
    const int dir = chain >> 13;
    const int b = (chain >> 9) & 15;
    const int i = chain & 511;

    const __half* u0 = U  + (size_t)b * NDIM + dir * 1536 + i;
    const float* x0 = Xin + (size_t)b * DIN  + dir * 512  + i;
    const size_t hoff = (size_t)b * DIN + dir * 512 + i;
    const int ustep = BATCH * NDIM;
    const int xstep = BATCH * DIN;

    // half-buffer position (permuted + row-swizzled; row&3 == b&3)
    const int kk = dir * 512 + i;
    const int pp = (kk & 15) >> 1;
    const int pos = (kk & ~15) + (((pp & 3) ^ (b & 3)) << 2)
                  + ((pp >> 2) << 1) + (kk & 1);
    const size_t hposoff = (size_t)b * DIN + pos;

    float c = ce[g * NCHAIN + chain];
    const int l0 = g * CH;
    #pragma unroll 8
    for (int t = 0; t < CH; t++) {
        const int l = dir ? (l0 + CH - 1 - t) : (l0 + t);
        const __half* up = u0 + (size_t)l * ustep;
        float xt = __half2float(__ldg(up));
        float f  = __half2float(__ldg(up + 512));
        float r  = __half2float(__ldg(up + 1024));
        float xp = __ldg(x0 + (size_t)l * xstep);
        c = f * c + (1.f - f) * xt;
        float h = r * tanh_fast(c) + (1.f - r) * xp;
        Xout[(size_t)l * xstep + hoff] = h;
        if (XoutH)
            XoutH[(size_t)l * xstep + hposoff] = __float2half_rn(h);
    }
}

// ---------------------------------------------------------------------------
// Launch
// ---------------------------------------------------------------------------
extern "C" void kernel_launch(void* const* d_in, const int* in_sizes, int n_in,
                              void* d_out, int out_size) {
    const int*   tok = (const int*)d_in[0];
    const float* emb = (const float*)d_in[2];
    const float* Ws  = (const float*)d_in[3];
    const float* bs  = (const float*)d_in[4];
    float* out = (float*)d_out;

    float *x0, *x1, *gF, *gC, *gce;
    __half *xh, *u;
    unsigned* wh;
    cudaGetSymbolAddress((void**)&x0, g_x0);
    cudaGetSymbolAddress((void**)&x1, g_x1);
    cudaGetSymbolAddress((void**)&xh, g_xh);
    cudaGetSymbolAddress((void**)&wh, g_wh);
    cudaGetSymbolAddress((void**)&u,  g_u);
    cudaGetSymbolAddress((void**)&gF, g_F);
    cudaGetSymbolAddress((void**)&gC, g_C);
    cudaGetSymbolAddress((void**)&gce, g_ce);

    cudaFuncSetAttribute(gemm_f16_kernel,
                         cudaFuncAttributeMaxDynamicSharedMemorySize, SMEM_BYTES);

    // Pre-pack weights to half2 pairs
    wconv_kernel<<<(NLAY * (KDIM/2) * (NDIM/4)) / 256, 256>>>(Ws, wh);

    // Embedding gather
    gather_kernel<<<(MROWS * DIN / 4) / 256, 256>>>(tok, emb, x0, xh);

    float* xcur = x0;
    float* xalt = x1;
    float* hid_base = out + (size_t)MROWS * DIN;

    dim3 ggrid(NDIM / 256, MROWS / 128);        // (12, 128)
    const int scan_blocks = (NCH * NCHAIN) / 256;  // 1024

    for (int l = 0; l < NLAY; l++) {
        const unsigned* Wl = wh + (size_t)l * (KDIM/2) * NDIM;
        const float* bl = bs + (size_t)l * 2048;
        gemm_f16_kernel<<<ggrid, 256, SMEM_BYTES>>>(xh, Wl, bl, u);

        float* xnext = (l == NLAY - 1) ? out : xalt;
        __half* xhnext = (l == NLAY - 1) ? nullptr : xh;
        float* cout_l = hid_base + (size_t)l * BATCH * DIN;

        scan1_kernel<<<scan_blocks, 256>>>(u, gF, gC);
        scan2_kernel<<<NCHAIN / 256, 256>>>(gF, gC, gce, cout_l);
        scan3_kernel<<<scan_blocks, 256>>>(u, xcur, gce, xnext, xhnext);

        xalt = xcur;
        xcur = xnext;
    }
}

// round 11
// speedup vs baseline: 1.7558x; 1.0320x over previous
#include <cuda_runtime.h>
#include <cuda_fp16.h>
#include <cstdint>

// Problem constants
#define LSEQ  1024
#define BATCH 16
#define DIN   1024
#define NOUT  512
#define NLAY  4
#define MROWS (LSEQ*BATCH)   // 16384
#define KDIM  1024
#define NDIM  3072           // 6 * NOUT
#define NCH   16             // scan chunks
#define CH    64             // steps per chunk
#define NCHAIN 16384         // 2*B*NOUT

// GEMM: block 128x256, BK=32, 256 threads, 8 warps (2x4) of 64x64 tiles
#define GK    32
#define NKT   (KDIM/GK)      // 32
#define A_BUF_B 8192         // 2 planes x 128 rows x 32B
#define B_ROW_B 1056         // 264 uints
#define B_BUF_B (16 * B_ROW_B)   // 16896
#define SMEM_BYTES (2*A_BUF_B + 2*B_BUF_B)   // 50176

// Scratch (device globals: allocation-free)
__device__ __half   g_xh[MROWS * DIN];          // half x, permuted+swizzled (in-place across layers)
__device__ unsigned g_wh[NLAY * (KDIM/2) * NDIM]; // pair-packed half2 W
__device__ __half   g_u [MROWS * NDIM];         // gate activations (fp16)
__device__ float    g_F [NCH * NCHAIN];
__device__ float    g_C [NCH * NCHAIN];
__device__ float    g_ce[NCH * NCHAIN];

__device__ __forceinline__ float tanh_fast(float x) {
    float y;
    asm("tanh.approx.f32 %0, %1;" : "=f"(y) : "f"(x));
    return y;
}
__device__ __forceinline__ uint32_t smem_u32(const void* p) {
    uint32_t a;
    asm("{ .reg .u64 t; cvta.to.shared.u64 t, %1; cvt.u32.u64 %0, t; }"
        : "=r"(a) : "l"(p));
    return a;
}
__device__ __forceinline__ void cp_async16(uint32_t dst, const void* src) {
    asm volatile("cp.async.cg.shared.global [%0], [%1], 16;"
                 :: "r"(dst), "l"(src) : "memory");
}
__device__ __forceinline__ unsigned packh2(float lo, float hi) {
    __half2 h = __floats2half2_rn(lo, hi);
    return *reinterpret_cast<unsigned*>(&h);
}
__device__ __forceinline__ void mma_f16(float c[4],
                                        unsigned a0, unsigned a1,
                                        unsigned a2, unsigned a3,
                                        unsigned b0, unsigned b1) {
    asm volatile(
        "mma.sync.aligned.m16n8k16.row.col.f32.f16.f16.f32 "
        "{%0,%1,%2,%3}, {%4,%5,%6,%7}, {%8,%9}, {%0,%1,%2,%3};"
        : "+f"(c[0]), "+f"(c[1]), "+f"(c[2]), "+f"(c[3])
        : "r"(a0), "r"(a1), "r"(a2), "r"(a3), "r"(b0), "r"(b1));
}
// position of even k-pair start within permuted+swizzled row
__device__ __forceinline__ int permpos_pair(int k, int row) {
    int pp = (k & 15) >> 1;
    return (k & ~15) + ((((pp & 3) ^ (row & 3))) << 2) + ((pp >> 2) << 1);
}

// ---------------------------------------------------------------------------
// Weight pre-pack (once): wh[l][p][n] = half2( W[l][2p][n], W[l][2p+1][n] )
// ---------------------------------------------------------------------------
__global__ void wconv_kernel(const float* __restrict__ W, unsigned* __restrict__ Wp) {
    int e = blockIdx.x * blockDim.x + threadIdx.x;
    int n4 = e % (NDIM / 4);
    int tmp = e / (NDIM / 4);
    int p = tmp % (KDIM / 2);
    int l = tmp / (KDIM / 2);
    const float* base = W + (size_t)l * KDIM * NDIM + (size_t)(2 * p) * NDIM + n4 * 4;
    float4 r0 = *reinterpret_cast<const float4*>(base);
    float4 r1 = *reinterpret_cast<const float4*>(base + NDIM);
    uint4 u;
    u.x = packh2(r0.x, r1.x);
    u.y = packh2(r0.y, r1.y);
    u.z = packh2(r0.z, r1.z);
    u.w = packh2(r0.w, r1.w);
    reinterpret_cast<uint4*>(Wp + ((size_t)l * (KDIM/2) + p) * NDIM)[n4] = u;
}

// ---------------------------------------------------------------------------
// Embedding gather -> permuted half x only
// ---------------------------------------------------------------------------
__global__ void gather_kernel(const int* __restrict__ tok,
                              const float* __restrict__ emb,
                              __half* __restrict__ outH) {
    int e = blockIdx.x * blockDim.x + threadIdx.x;
    int row = e >> 8;
    int d4  = e & 255;
    int t = tok[row];
    float4 v = reinterpret_cast<const float4*>(emb + (size_t)t * DIN)[d4];
    int k0 = d4 * 4;
    __half2 h01 = __floats2half2_rn(v.x, v.y);
    __half2 h23 = __floats2half2_rn(v.z, v.w);
    __half* xr = outH + (size_t)row * DIN;
    *reinterpret_cast<__half2*>(xr + permpos_pair(k0, row))     = h01;
    *reinterpret_cast<__half2*>(xr + permpos_pair(k0 + 2, row)) = h23;
}

// ---------------------------------------------------------------------------
// FP16 GEMM: U = X(M,K)*W(K,N). mma.sync m16n8k16 f16 -> fp32 acc.
// (unchanged winner from round 10)
// ---------------------------------------------------------------------------
__global__ void __launch_bounds__(256, 1)
gemm_f16_kernel(const __half* __restrict__ Xh,
                const unsigned* __restrict__ Wp,
                const float* __restrict__ bias,
                __half* __restrict__ U) {
    extern __shared__ char sm[];
    char* Abuf = sm;                    // 2 * A_BUF_B
    char* Bbuf = sm + 2 * A_BUF_B;      // 2 * B_BUF_B
    const uint32_t a_s = smem_u32(Abuf);
    const uint32_t b_s = smem_u32(Bbuf);

    const int tid  = threadIdx.x;
    const int lane = tid & 31;
    const int warp = tid >> 5;
    const int wm = warp >> 2;        // 0..1
    const int wn = warp & 3;         // 0..3
    const int q = lane >> 2;         // 0..7
    const int j = lane & 3;          // 0..3
    const int rowBase = blockIdx.y * 128;
    const int colBase = blockIdx.x * 256;

    const char* Ag = reinterpret_cast<const char*>(Xh + (size_t)rowBase * DIN);
    const unsigned* Bg = Wp + colBase;

    float acc[4][8][4];
    #pragma unroll
    for (int mf = 0; mf < 4; mf++)
        #pragma unroll
        for (int nf = 0; nf < 8; nf++)
            #pragma unroll
            for (int e = 0; e < 4; e++) acc[mf][nf][e] = 0.f;

    auto cpStage = [&](int buf, int kt) {
        #pragma unroll
        for (int t = 0; t < 2; t++) {
            int v = tid + t * 256;
            int r = v >> 2, c = v & 3;
            cp_async16(a_s + buf * A_BUF_B + (c >> 1) * 4096 + r * 32 + (c & 1) * 16,
                       Ag + (size_t)r * (DIN * 2) + kt * 64 + c * 16);
        }
        #pragma unroll
        for (int t = 0; t < 4; t++) {
            int v = tid + t * 256;
            int p = v >> 6, nc = v & 63;
            cp_async16(b_s + buf * B_BUF_B + p * B_ROW_B + nc * 16,
                       Bg + (size_t)(kt * 16 + p) * NDIM + nc * 4);
        }
        asm volatile("cp.async.commit_group;" ::: "memory");
    };

    cpStage(0, 0);
    int buf = 0;

    for (int kt = 0; kt < NKT; kt++) {
        asm volatile("cp.async.wait_group 0;" ::: "memory");
        __syncthreads();
        if (kt < NKT - 1) cpStage(buf ^ 1, kt + 1);

        #pragma unroll
        for (int s = 0; s < 2; s++) {
            const char* ab = Abuf + buf * A_BUF_B + s * 4096;
            uint2 alo[4], ahi[4];
            #pragma unroll
            for (int mf = 0; mf < 4; mf++) {
                int r = wm * 64 + mf * 16 + q;
                int sw = (j ^ (r & 3)) * 8;
                alo[mf] = *reinterpret_cast<const uint2*>(ab + r * 32 + sw);
                ahi[mf] = *reinterpret_cast<const uint2*>(ab + (r + 8) * 32 + sw);
            }
            const char* bb = Bbuf + buf * B_BUF_B + (s * 8 + j) * B_ROW_B
                           + (wn * 64 + q) * 4;
            unsigned b0[8], b1[8];
            #pragma unroll
            for (int nf = 0; nf < 8; nf++) {
                b0[nf] = *reinterpret_cast<const unsigned*>(bb + nf * 32);
                b1[nf] = *reinterpret_cast<const unsigned*>(bb + 4 * B_ROW_B + nf * 32);
            }
            #pragma unroll
            for (int mf = 0; mf < 4; mf++)
                #pragma unroll
                for (int nf = 0; nf < 8; nf++)
                    mma_f16(acc[mf][nf],
                            alo[mf].x, ahi[mf].x, alo[mf].y, ahi[mf].y,
                            b0[nf], b1[nf]);
        }
        buf ^= 1;
    }

    // Epilogue: warp's 64-col slice lies within one 512-col block (64 | 512)
    const int wcol = colBase + wn * 64;
    const int dir  = wcol / 1536;
    const int cm   = wcol - dir * 1536;
    int btype = 0;
    const float* bptr = bias;
    if (cm >= 1024)      { btype = 2; bptr = bias + 1024 + dir * 512 + (cm - 1024); }
    else if (cm >= 512)  { btype = 1; bptr = bias + dir * 512 + (cm - 512); }

    #pragma unroll
    for (int nf = 0; nf < 8; nf++) {
        const int coff = nf * 8 + 2 * j;
        float bv0 = 0.f, bv1 = 0.f;
        if (btype) { bv0 = bptr[coff]; bv1 = bptr[coff + 1]; }
        const int col = wcol + coff;
        #pragma unroll
        for (int mf = 0; mf < 4; mf++) {
            const int row0 = rowBase + wm * 64 + mf * 16 + q;
            float v0 = acc[mf][nf][0], v1 = acc[mf][nf][1];
            float v2 = acc[mf][nf][2], v3 = acc[mf][nf][3];
            if (btype) {
                v0 = 1.f / (1.f + __expf(-(v0 + bv0)));
                v1 = 1.f / (1.f + __expf(-(v1 + bv1)));
                v2 = 1.f / (1.f + __expf(-(v2 + bv0)));
                v3 = 1.f / (1.f + __expf(-(v3 + bv1)));
            }
            *reinterpret_cast<__half2*>(&U[(size_t)row0 * NDIM + col])
                = __floats2half2_rn(v0, v1);
            *reinterpret_cast<__half2*>(&U[(size_t)(row0 + 8) * NDIM + col])
                = __floats2half2_rn(v2, v3);
        }
    }
}

// ---------------------------------------------------------------------------
// Chunked SRU scan (3-pass), 2 chains per thread via half2.
// Pair = chains (chain, chain+1), chain even. Chain = dir*8192 + b*512 + i.
// ---------------------------------------------------------------------------
__global__ void scan1_kernel(const __half* __restrict__ U,
                             float* __restrict__ Fo, float* __restrict__ Co) {
    const int idx = blockIdx.x * blockDim.x + threadIdx.x;  // 0..NCH*NCHAIN/2-1
    const int pairc = idx & (NCHAIN / 2 - 1);
    const int g = idx >> 13;
    const int chain = pairc * 2;
    const int dir = chain >> 13;
    const int b = (chain >> 9) & 15;
    const int i = chain & 511;

    const __half* u0 = U + (size_t)b * NDIM + dir * 1536 + i;
    const int ustep = BATCH * NDIM;

    float2 F = make_float2(1.f, 1.f), C = make_float2(0.f, 0.f);
    const int l0 = g * CH;
    #pragma unroll 8
    for (int t = 0; t < CH; t++) {
        const int l = dir ? (l0 + CH - 1 - t) : (l0 + t);
        const __half* up = u0 + (size_t)l * ustep;
        float2 xt = __half22float2(__ldg(reinterpret_cast<const __half2*>(up)));
        float2 f  = __half22float2(__ldg(reinterpret_cast<const __half2*>(up + 512)));
        C.x = f.x * C.x + (1.f - f.x) * xt.x;
        C.y = f.y * C.y + (1.f - f.y) * xt.y;
        F.x *= f.x;
        F.y *= f.y;
    }
    *reinterpret_cast<float2*>(&Fo[idx * 2]) = F;
    *reinterpret_cast<float2*>(&Co[idx * 2]) = C;
}

__global__ void scan2_kernel(const float* __restrict__ Fo, const float* __restrict__ Co,
                             float* __restrict__ ce, float* __restrict__ Cout) {
    const int chain = blockIdx.x * blockDim.x + threadIdx.x;
    const int dir = chain >> 13;
    const int b = (chain >> 9) & 15;
    const int i = chain & 511;

    float c = 0.f;
    #pragma unroll
    for (int t = 0; t < NCH; t++) {
        int g = dir ? (NCH - 1 - t) : t;
        ce[g * NCHAIN + chain] = c;
        c = Fo[g * NCHAIN + chain] * c + Co[g * NCHAIN + chain];
    }
    Cout[b * 1024 + dir * 512 + i] = c;
}

__global__ void scan3_kernel(const __half* __restrict__ U,
                             const float* __restrict__ ce,
                             __half* __restrict__ Xh,      // in-place x (read xp / write h)
                             float* __restrict__ OutF) {   // non-null on last layer
    const int idx = blockIdx.x * blockDim.x + threadIdx.x;
    const int pairc = idx & (NCHAIN / 2 - 1);
    const int g = idx >> 13;
    const int chain = pairc * 2;
    const int dir = chain >> 13;
    const int b = (chain >> 9) & 15;
    const int i = chain & 511;

    const __half* u0 = U + (size_t)b * NDIM + dir * 1536 + i;
    const int ustep = BATCH * NDIM;
    const int xstep = BATCH * DIN;

    // permuted half-x position for even kk: pair (pos, pos+1). row&3 == b&3.
    const int kk = dir * 512 + i;
    const size_t hposoff = (size_t)b * DIN + permpos_pair(kk, b);
    const size_t foff    = (size_t)b * DIN + dir * 512 + i;

    float2 c2 = *reinterpret_cast<const float2*>(&ce[g * NCHAIN + chain]);
    const int l0 = g * CH;
    #pragma unroll 8
    for (int t = 0; t < CH; t++) {
        const int l = dir ? (l0 + CH - 1 - t) : (l0 + t);
        const __half* up = u0 + (size_t)l * ustep;
        float2 xt = __half22float2(__ldg(reinterpret_cast<const __half2*>(up)));
        float2 f  = __half22float2(__ldg(reinterpret_cast<const __half2*>(up + 512)));
        float2 r  = __half22float2(__ldg(reinterpret_cast<const __half2*>(up + 1024)));
        __half2* xpp = reinterpret_cast<__half2*>(Xh + (size_t)l * xstep + hposoff);
        float2 xp = __half22float2(*xpp);
        c2.x = f.x * c2.x + (1.f - f.x) * xt.x;
        c2.y = f.y * c2.y + (1.f - f.y) * xt.y;
        float h0 = r.x * tanh_fast(c2.x) + (1.f - r.x) * xp.x;
        float h1 = r.y * tanh_fast(c2.y) + (1.f - r.y) * xp.y;
        if (OutF) {
            *reinterpret_cast<float2*>(&OutF[(size_t)l * xstep + foff])
                = make_float2(h0, h1);
        } else {
            *xpp = __floats2half2_rn(h0, h1);
        }
    }
}

// ---------------------------------------------------------------------------
// Launch
// ---------------------------------------------------------------------------
extern "C" void kernel_launch(void* const* d_in, const int* in_sizes, int n_in,
                              void* d_out, int out_size) {
    const int*   tok = (const int*)d_in[0];
    const float* emb = (const float*)d_in[2];
    const float* Ws  = (const float*)d_in[3];
    const float* bs  = (const float*)d_in[4];
    float* out = (float*)d_out;

    float *gF, *gC, *gce;
    __half *xh, *u;
    unsigned* wh;
    cudaGetSymbolAddress((void**)&xh, g_xh);
    cudaGetSymbolAddress((void**)&wh, g_wh);
    cudaGetSymbolAddress((void**)&u,  g_u);
    cudaGetSymbolAddress((void**)&gF, g_F);
    cudaGetSymbolAddress((void**)&gC, g_C);
    cudaGetSymbolAddress((void**)&gce, g_ce);

    cudaFuncSetAttribute(gemm_f16_kernel,
                         cudaFuncAttributeMaxDynamicSharedMemorySize, SMEM_BYTES);

    // Pre-pack weights to half2 pairs
    wconv_kernel<<<(NLAY * (KDIM/2) * (NDIM/4)) / 256, 256>>>(Ws, wh);

    // Embedding gather
    gather_kernel<<<(MROWS * DIN / 4) / 256, 256>>>(tok, emb, xh);

    float* hid_base = out + (size_t)MROWS * DIN;

    dim3 ggrid(NDIM / 256, MROWS / 128);             // (12, 128)
    const int scan13_blocks = (NCH * NCHAIN / 2) / 256;  // 512

    for (int l = 0; l < NLAY; l++) {
        const unsigned* Wl = wh + (size_t)l * (KDIM/2) * NDIM;
        const float* bl = bs + (size_t)l * 2048;
        gemm_f16_kernel<<<ggrid, 256, SMEM_BYTES>>>(xh, Wl, bl, u);

        float* outF = (l == NLAY - 1) ? out : nullptr;
        float* cout_l = hid_base + (size_t)l * BATCH * DIN;

        scan1_kernel<<<scan13_blocks, 256>>>(u, gF, gC);
        scan2_kernel<<<NCHAIN / 256, 256>>>(gF, gC, gce, cout_l);
        scan3_kernel<<<scan13_blocks, 256>>>(u, gce, xh, outF);
    }
}